// round 8
// baseline (speedup 1.0000x reference)
#include <cuda_runtime.h>
#include <cuda_fp16.h>
#include <cstdint>
#include <cstddef>

#define S_LEN 4096
#define BATCH 8
#define DDIM  1024
#define HDIM  1024
#define MROWS (BATCH * S_LEN)   // 32768
#define NCHUNK 32
#define CHLEN  128              // S_LEN / NCHUNK

// ---------------- scratch (device globals; no allocations allowed) ----------
__device__ __half g_z[(size_t)MROWS * HDIM];                // sigmoid(x@Wz^T+bz)
__device__ __half g_g[(size_t)MROWS * HDIM];                // g(x@Wh^T+bh)
__device__ __half g_x16[(size_t)MROWS * DDIM];
__device__ __half g_wz16[(size_t)HDIM * DDIM];
__device__ __half g_wh16[(size_t)HDIM * DDIM];
__device__ float g_A[(size_t)BATCH * NCHUNK * HDIM];        // per-chunk prod(a)
__device__ float g_B[(size_t)BATCH * NCHUNK * HDIM];        // per-chunk h | h0=0

// ---------------- helpers ----------------------------------------------------
__device__ __forceinline__ uint32_t smem_u32(const void* p) {
    uint32_t a;
    asm("{ .reg .u64 t; cvta.to.shared.u64 t, %1; cvt.u32.u64 %0, t; }"
        : "=r"(a) : "l"(p));
    return a;
}
__device__ __forceinline__ void cp_async16(uint32_t dst, const void* src) {
    asm volatile("cp.async.cg.shared.global [%0], [%1], 16;"
                 :: "r"(dst), "l"(src) : "memory");
}
__device__ __forceinline__ void cp_commit() {
    asm volatile("cp.async.commit_group;" ::: "memory");
}
template <int N>
__device__ __forceinline__ void cp_wait() {
    asm volatile("cp.async.wait_group %0;" :: "n"(N) : "memory");
}
__device__ __forceinline__ void ldsm_x4(uint32_t& r0, uint32_t& r1,
                                        uint32_t& r2, uint32_t& r3, uint32_t addr) {
    asm volatile("ldmatrix.sync.aligned.m8n8.x4.shared.b16 {%0,%1,%2,%3}, [%4];"
                 : "=r"(r0), "=r"(r1), "=r"(r2), "=r"(r3) : "r"(addr));
}
__device__ __forceinline__ void mma16816(float* d, const uint32_t* a, const uint32_t* b) {
    asm volatile(
        "mma.sync.aligned.m16n8k16.row.col.f32.f16.f16.f32 "
        "{%0,%1,%2,%3}, {%4,%5,%6,%7}, {%8,%9}, {%0,%1,%2,%3};"
        : "+f"(d[0]), "+f"(d[1]), "+f"(d[2]), "+f"(d[3])
        : "r"(a[0]), "r"(a[1]), "r"(a[2]), "r"(a[3]), "r"(b[0]), "r"(b[1]));
}
__device__ __forceinline__ uint32_t sw128(uint32_t off) {
    return off ^ ((off >> 3) & 0x70);
}

__device__ __forceinline__ float sigf(float x) { return 1.f / (1.f + __expf(-x)); }
__device__ __forceinline__ float gfun(float x) { return (x >= 0.f) ? (x + 0.5f) : sigf(x); }

// ---------------- fp32 -> fp16 convert (one launch) --------------------------
#define X_N4  (MROWS * DDIM / 4)     // 8388608
#define W_N4  (HDIM * DDIM / 4)      // 262144
__global__ void convert_all(const float* __restrict__ x,
                            const float* __restrict__ Wz,
                            const float* __restrict__ Wh)
{
    int i = blockIdx.x * blockDim.x + threadIdx.x;
    const float* src;
    __half* dst;
    int idx;
    if (i < X_N4)                 { src = x;  dst = g_x16;  idx = i; }
    else if (i < X_N4 + W_N4)     { src = Wz; dst = g_wz16; idx = i - X_N4; }
    else if (i < X_N4 + 2 * W_N4) { src = Wh; dst = g_wh16; idx = i - X_N4 - W_N4; }
    else return;
    float4 v = ((const float4*)src)[idx];
    __half2* dp = (__half2*)(dst + (size_t)idx * 4);
    dp[0] = __halves2half2(__float2half_rn(v.x), __float2half_rn(v.y));
    dp[1] = __halves2half2(__float2half_rn(v.z), __float2half_rn(v.w));
}

// ---------------- HMMA GEMM (fp16 in, fp32 accum) + fused nonlinearity -------
// z-jobs:  g_z = sigmoid(X@Wz^T + bz)  (fp16)
// h-jobs:  g_g = g(X@Wh^T + bh)        (fp16)
// CTA 128x128, 8 warps 2(m) x 4(n), warp tile 64x32. K-chunk 64, SW128.
// 3-stage cp.async pipeline. K=1024 -> 16 chunks.
#define KCH 64
#define NITER 16
#define STAGE_BYTES 32768

__global__ void __launch_bounds__(256)
gemm_mma(const float* __restrict__ bz, const float* __restrict__ bh)
{
    __shared__ __align__(1024) uint8_t smem[3 * STAGE_BYTES];

    const int tid = threadIdx.x, wid = tid >> 5, lane = tid & 31;
    const int wm = wid >> 2, wn = wid & 3;     // 2 x 4 warp grid
    const bool is_z = (blockIdx.x < 8);
    const int n0 = (is_z ? blockIdx.x : blockIdx.x - 8) * 128;
    const int m0 = blockIdx.y * 128;
    const __half* W = is_z ? g_wz16 : g_wh16;
    const float* bias = is_z ? bz : bh;
    __half* C = is_z ? g_z : g_g;

    const uint32_t sbase = smem_u32(smem);

    float acc[4][4][4];   // [mi][nj][frag]
#pragma unroll
    for (int i = 0; i < 4; i++)
#pragma unroll
        for (int j = 0; j < 4; j++)
#pragma unroll
            for (int f = 0; f < 4; f++) acc[i][j][f] = 0.f;

    auto issue = [&](int ch, int st) {
        const int kc = ch * KCH;
        const uint32_t stb = sbase + st * STAGE_BYTES;
#pragma unroll
        for (int i = 0; i < 4; i++) {
            int s = tid + i * 256;              // 1024 slots of 16B per tile
            int row = s >> 3, kslot = s & 7;
            uint32_t off = sw128(row * 128 + kslot * 16);
            cp_async16(stb + off,
                       g_x16 + (size_t)(m0 + row) * DDIM + kc + kslot * 8);
            cp_async16(stb + 16384 + off,
                       W + (size_t)(n0 + row) * DDIM + kc + kslot * 8);
        }
        cp_commit();
    };

    issue(0, 0);
    issue(1, 1);

    int st = 0;
    for (int ch = 0; ch < NITER; ch++) {
        if (ch + 2 < NITER) cp_wait<1>(); else cp_wait<0>();
        __syncthreads();
        if (ch + 2 < NITER) issue(ch + 2, (st + 2) % 3);

        const uint32_t aB = sbase + st * STAGE_BYTES;
        const uint32_t bB = aB + 16384;

#pragma unroll
        for (int ks = 0; ks < 4; ks++) {        // 4 x k16 per chunk
            uint32_t af[4][4], bf[2][4];
#pragma unroll
            for (int mi = 0; mi < 4; mi++) {
                int row = wm * 64 + mi * 16 + (lane & 15);
                uint32_t off = sw128(row * 128 + ks * 32 + (lane >> 4) * 16);
                ldsm_x4(af[mi][0], af[mi][1], af[mi][2], af[mi][3], aB + off);
            }
#pragma unroll
            for (int bj = 0; bj < 2; bj++) {
                int row = wn * 32 + bj * 16 + (lane & 7) + ((lane >> 4) & 1) * 8;
                uint32_t off = sw128(row * 128 + ks * 32 + ((lane >> 3) & 1) * 16);
                ldsm_x4(bf[bj][0], bf[bj][1], bf[bj][2], bf[bj][3], bB + off);
            }
#pragma unroll
            for (int mi = 0; mi < 4; mi++) {
#pragma unroll
                for (int bj = 0; bj < 2; bj++) {
                    mma16816(acc[mi][bj * 2],     af[mi], &bf[bj][0]);
                    mma16816(acc[mi][bj * 2 + 1], af[mi], &bf[bj][2]);
                }
            }
        }
        st = (st + 1) % 3;
    }

    // epilogue: bias + nonlinearity, fp16 stores
#pragma unroll
    for (int mi = 0; mi < 4; mi++) {
#pragma unroll
        for (int nj = 0; nj < 4; nj++) {
            int mrow = m0 + wm * 64 + mi * 16 + (lane >> 2);
            int ncol = n0 + wn * 32 + nj * 8 + (lane & 3) * 2;
            float2 bv = *(const float2*)(bias + ncol);
            float v[4] = {acc[mi][nj][0] + bv.x, acc[mi][nj][1] + bv.y,
                          acc[mi][nj][2] + bv.x, acc[mi][nj][3] + bv.y};
            float r[4];
            if (is_z) {
#pragma unroll
                for (int f = 0; f < 4; f++) r[f] = sigf(v[f]);
            } else {
#pragma unroll
                for (int f = 0; f < 4; f++) r[f] = gfun(v[f]);
            }
            __half2 h0 = __halves2half2(__float2half_rn(r[0]), __float2half_rn(r[1]));
            __half2 h1 = __halves2half2(__float2half_rn(r[2]), __float2half_rn(r[3]));
            *(__half2*)(C + (size_t)mrow * HDIM + ncol) = h0;
            *(__half2*)(C + (size_t)(mrow + 8) * HDIM + ncol) = h1;
        }
    }
}

// ---------------- scan: h_t = (1-z_t) h_{t-1} + z_t g_t ----------------------
// pass 1: per-chunk (A = prod (1-z), B = h with h_start=0)
__global__ void scan_p1()
{
    const int h  = blockIdx.x * 128 + threadIdx.x;
    const int ch = blockIdx.y;
    const int b  = blockIdx.z;
    const size_t base = ((size_t)(b * S_LEN + ch * CHLEN)) * HDIM + h;
    const __half* zp = g_z + base;
    const __half* gp = g_g + base;
    float A = 1.f, hB = 0.f;
    for (int s0 = 0; s0 < CHLEN; s0 += 8) {
        float zz[8], gg[8];
#pragma unroll
        for (int j = 0; j < 8; j++) {
            zz[j] = __half2float(zp[(size_t)(s0 + j) * HDIM]);
            gg[j] = __half2float(gp[(size_t)(s0 + j) * HDIM]);
        }
#pragma unroll
        for (int j = 0; j < 8; j++) {
            float a = 1.f - zz[j];
            hB = fmaf(a, hB, zz[j] * gg[j]);
            A *= a;
        }
    }
    const size_t ci = ((size_t)(b * NCHUNK + ch)) * HDIM + h;
    g_A[ci] = A;
    g_B[ci] = hB;
}

// pass 2 folded into pass 3: each block rebuilds its chunk-prefix state from
// g_A/g_B (hot in L2), then re-runs its chunk emitting outputs.
__global__ void scan_p3(const float* __restrict__ h0, float* __restrict__ out)
{
    const int h  = blockIdx.x * 128 + threadIdx.x;
    const int ch = blockIdx.y;
    const int b  = blockIdx.z;

    float x0 = h0[b * HDIM + h];
    float hc = gfun(x0);
    for (int c = 0; c < ch; c++) {
        const size_t ci = ((size_t)(b * NCHUNK + c)) * HDIM + h;
        hc = fmaf(g_A[ci], hc, g_B[ci]);
    }

    const size_t base = ((size_t)(b * S_LEN + ch * CHLEN)) * HDIM + h;
    const __half* zp = g_z + base;
    const __half* gp = g_g + base;
    float* op = out + base;
    for (int s0 = 0; s0 < CHLEN; s0 += 8) {
        float zz[8], gg[8];
#pragma unroll
        for (int j = 0; j < 8; j++) {
            zz[j] = __half2float(zp[(size_t)(s0 + j) * HDIM]);
            gg[j] = __half2float(gp[(size_t)(s0 + j) * HDIM]);
        }
#pragma unroll
        for (int j = 0; j < 8; j++) {
            hc = fmaf(zz[j], gg[j] - hc, hc);
            op[(size_t)(s0 + j) * HDIM] = hc;
        }
    }
}

// ---------------- launch ------------------------------------------------------
extern "C" void kernel_launch(void* const* d_in, const int* in_sizes, int n_in,
                              void* d_out, int out_size)
{
    const float* x  = (const float*)d_in[0];
    const float* h0 = (const float*)d_in[1];
    const float* Wz = (const float*)d_in[2];
    const float* bz = (const float*)d_in[3];
    const float* Wh = (const float*)d_in[4];
    const float* bh = (const float*)d_in[5];
    float* out = (float*)d_out;

    convert_all<<<(X_N4 + 2 * W_N4 + 255) / 256, 256>>>(x, Wz, Wh);

    dim3 ggrid(16, MROWS / 128);
    gemm_mma<<<ggrid, 256>>>(bz, bh);

    dim3 sgrid(HDIM / 128, NCHUNK, BATCH);
    scan_p1<<<sgrid, 128>>>();
    scan_p3<<<sgrid, 128>>>(h0, out);
}

// round 9
// speedup vs baseline: 1.0497x; 1.0497x over previous
#include <cuda_runtime.h>
#include <cuda_fp16.h>
#include <cstdint>
#include <cstddef>

#define S_LEN 4096
#define BATCH 8
#define DDIM  1024
#define HDIM  1024
#define MROWS (BATCH * S_LEN)   // 32768
#define NCHUNK 32
#define CHLEN  128              // S_LEN / NCHUNK

// ---------------- scratch (device globals; no allocations allowed) ----------
__device__ float g_k[(size_t)MROWS * HDIM];                 // x@Wz^T+bz
__device__ float g_t[(size_t)MROWS * HDIM];                 // x@Wh^T+bh
__device__ __half g_x16[(size_t)MROWS * DDIM];
__device__ __half g_wz16[(size_t)HDIM * DDIM];
__device__ __half g_wh16[(size_t)HDIM * DDIM];
__device__ float g_A[(size_t)BATCH * NCHUNK * HDIM];        // per-chunk prod(a)
__device__ float g_B[(size_t)BATCH * NCHUNK * HDIM];        // per-chunk h | h0=0

// ---------------- helpers ----------------------------------------------------
__device__ __forceinline__ uint32_t smem_u32(const void* p) {
    uint32_t a;
    asm("{ .reg .u64 t; cvta.to.shared.u64 t, %1; cvt.u32.u64 %0, t; }"
        : "=r"(a) : "l"(p));
    return a;
}
__device__ __forceinline__ void cp_async16(uint32_t dst, const void* src) {
    asm volatile("cp.async.cg.shared.global [%0], [%1], 16;"
                 :: "r"(dst), "l"(src) : "memory");
}
__device__ __forceinline__ void cp_commit() {
    asm volatile("cp.async.commit_group;" ::: "memory");
}
template <int N>
__device__ __forceinline__ void cp_wait() {
    asm volatile("cp.async.wait_group %0;" :: "n"(N) : "memory");
}
__device__ __forceinline__ void ldsm_x4(uint32_t& r0, uint32_t& r1,
                                        uint32_t& r2, uint32_t& r3, uint32_t addr) {
    asm volatile("ldmatrix.sync.aligned.m8n8.x4.shared.b16 {%0,%1,%2,%3}, [%4];"
                 : "=r"(r0), "=r"(r1), "=r"(r2), "=r"(r3) : "r"(addr));
}
__device__ __forceinline__ void mma16816(float* d, const uint32_t* a, const uint32_t* b) {
    asm volatile(
        "mma.sync.aligned.m16n8k16.row.col.f32.f16.f16.f32 "
        "{%0,%1,%2,%3}, {%4,%5,%6,%7}, {%8,%9}, {%0,%1,%2,%3};"
        : "+f"(d[0]), "+f"(d[1]), "+f"(d[2]), "+f"(d[3])
        : "r"(a[0]), "r"(a[1]), "r"(a[2]), "r"(a[3]), "r"(b[0]), "r"(b[1]));
}
__device__ __forceinline__ uint32_t sw128(uint32_t off) {
    return off ^ ((off >> 3) & 0x70);
}

__device__ __forceinline__ float sigf(float x) { return 1.f / (1.f + __expf(-x)); }
__device__ __forceinline__ float gfun(float x) { return (x >= 0.f) ? (x + 0.5f) : sigf(x); }

// ---------------- fp32 -> fp16 convert (one launch) --------------------------
#define X_N4  (MROWS * DDIM / 4)     // 8388608
#define W_N4  (HDIM * DDIM / 4)      // 262144
__global__ void convert_all(const float* __restrict__ x,
                            const float* __restrict__ Wz,
                            const float* __restrict__ Wh)
{
    int i = blockIdx.x * blockDim.x + threadIdx.x;
    const float* src;
    __half* dst;
    int idx;
    if (i < X_N4)                 { src = x;  dst = g_x16;  idx = i; }
    else if (i < X_N4 + W_N4)     { src = Wz; dst = g_wz16; idx = i - X_N4; }
    else if (i < X_N4 + 2 * W_N4) { src = Wh; dst = g_wh16; idx = i - X_N4 - W_N4; }
    else return;
    float4 v = ((const float4*)src)[idx];
    __half2* dp = (__half2*)(dst + (size_t)idx * 4);
    dp[0] = __halves2half2(__float2half_rn(v.x), __float2half_rn(v.y));
    dp[1] = __halves2half2(__float2half_rn(v.z), __float2half_rn(v.w));
}

// ---------------- HMMA GEMM (fp16 in, fp32 accum): C = X@W^T + bias ----------
// CTA 128x128, 8 warps 2(m) x 4(n), warp tile 64x32. K-chunk 64, SW128.
// 3-stage cp.async pipeline. K=1024 -> 16 chunks. (R7-proven: ~300us)
#define KCH 64
#define NITER 16
#define STAGE_BYTES 32768

__global__ void __launch_bounds__(256)
gemm_mma(const float* __restrict__ bz, const float* __restrict__ bh)
{
    __shared__ __align__(1024) uint8_t smem[3 * STAGE_BYTES];

    const int tid = threadIdx.x, wid = tid >> 5, lane = tid & 31;
    const int wm = wid >> 2, wn = wid & 3;     // 2 x 4 warp grid
    const bool is_z = (blockIdx.x < 8);
    const int n0 = (is_z ? blockIdx.x : blockIdx.x - 8) * 128;
    const int m0 = blockIdx.y * 128;
    const __half* W = is_z ? g_wz16 : g_wh16;
    const float* bias = is_z ? bz : bh;
    float* C = is_z ? g_k : g_t;

    const uint32_t sbase = smem_u32(smem);

    float acc[4][4][4];   // [mi][nj][frag]
#pragma unroll
    for (int i = 0; i < 4; i++)
#pragma unroll
        for (int j = 0; j < 4; j++)
#pragma unroll
            for (int f = 0; f < 4; f++) acc[i][j][f] = 0.f;

    auto issue = [&](int ch, int st) {
        const int kc = ch * KCH;
        const uint32_t stb = sbase + st * STAGE_BYTES;
#pragma unroll
        for (int i = 0; i < 4; i++) {
            int s = tid + i * 256;              // 1024 slots of 16B per tile
            int row = s >> 3, kslot = s & 7;
            uint32_t off = sw128(row * 128 + kslot * 16);
            cp_async16(stb + off,
                       g_x16 + (size_t)(m0 + row) * DDIM + kc + kslot * 8);
            cp_async16(stb + 16384 + off,
                       W + (size_t)(n0 + row) * DDIM + kc + kslot * 8);
        }
        cp_commit();
    };

    issue(0, 0);
    issue(1, 1);

    int st = 0;
    for (int ch = 0; ch < NITER; ch++) {
        if (ch + 2 < NITER) cp_wait<1>(); else cp_wait<0>();
        __syncthreads();
        if (ch + 2 < NITER) issue(ch + 2, (st + 2) % 3);

        const uint32_t aB = sbase + st * STAGE_BYTES;
        const uint32_t bB = aB + 16384;

#pragma unroll
        for (int ks = 0; ks < 4; ks++) {        // 4 x k16 per chunk
            uint32_t af[4][4], bf[2][4];
#pragma unroll
            for (int mi = 0; mi < 4; mi++) {
                int row = wm * 64 + mi * 16 + (lane & 15);
                uint32_t off = sw128(row * 128 + ks * 32 + (lane >> 4) * 16);
                ldsm_x4(af[mi][0], af[mi][1], af[mi][2], af[mi][3], aB + off);
            }
#pragma unroll
            for (int bj = 0; bj < 2; bj++) {
                int row = wn * 32 + bj * 16 + (lane & 7) + ((lane >> 4) & 1) * 8;
                uint32_t off = sw128(row * 128 + ks * 32 + ((lane >> 3) & 1) * 16);
                ldsm_x4(bf[bj][0], bf[bj][1], bf[bj][2], bf[bj][3], bB + off);
            }
#pragma unroll
            for (int mi = 0; mi < 4; mi++) {
#pragma unroll
                for (int bj = 0; bj < 2; bj++) {
                    mma16816(acc[mi][bj * 2],     af[mi], &bf[bj][0]);
                    mma16816(acc[mi][bj * 2 + 1], af[mi], &bf[bj][2]);
                }
            }
        }
        st = (st + 1) % 3;
    }

    // epilogue: direct stores + bias (fp32, coalesced float2 — R7-proven)
#pragma unroll
    for (int mi = 0; mi < 4; mi++) {
#pragma unroll
        for (int nj = 0; nj < 4; nj++) {
            int mrow = m0 + wm * 64 + mi * 16 + (lane >> 2);
            int ncol = n0 + wn * 32 + nj * 8 + (lane & 3) * 2;
            float2 bv = *(const float2*)(bias + ncol);
            float2 v0 = make_float2(acc[mi][nj][0] + bv.x, acc[mi][nj][1] + bv.y);
            float2 v1 = make_float2(acc[mi][nj][2] + bv.x, acc[mi][nj][3] + bv.y);
            *(float2*)(C + (size_t)mrow * HDIM + ncol) = v0;
            *(float2*)(C + (size_t)(mrow + 8) * HDIM + ncol) = v1;
        }
    }
}

// ---------------- scan: h_t = (1-z_t) h_{t-1} + z_t g(t_t) -------------------
// 4 channels per thread via float4 loads (4x fewer LDG issues vs R7 scalar).
// pass 1: per-chunk (A = prod (1-z), B = h with h_start=0)
__global__ void scan_p1()
{
    const int h  = (blockIdx.x * 128 + threadIdx.x) * 4;
    const int ch = blockIdx.y;
    const int b  = blockIdx.z;
    const size_t base = ((size_t)(b * S_LEN + ch * CHLEN)) * HDIM + h;
    const float* kp = g_k + base;
    const float* tp = g_t + base;
    float A[4] = {1.f, 1.f, 1.f, 1.f};
    float hB[4] = {0.f, 0.f, 0.f, 0.f};
    for (int s0 = 0; s0 < CHLEN; s0 += 4) {
        float4 kk[4], tt[4];
#pragma unroll
        for (int j = 0; j < 4; j++) {
            kk[j] = *(const float4*)(kp + (size_t)(s0 + j) * HDIM);
            tt[j] = *(const float4*)(tp + (size_t)(s0 + j) * HDIM);
        }
#pragma unroll
        for (int j = 0; j < 4; j++) {
            float kv[4] = {kk[j].x, kk[j].y, kk[j].z, kk[j].w};
            float tv[4] = {tt[j].x, tt[j].y, tt[j].z, tt[j].w};
#pragma unroll
            for (int c = 0; c < 4; c++) {
                float z = sigf(kv[c]);
                float a = 1.f - z;
                hB[c] = fmaf(a, hB[c], z * gfun(tv[c]));
                A[c] *= a;
            }
        }
    }
    const size_t ci = ((size_t)(b * NCHUNK + ch)) * HDIM + h;
    *(float4*)(g_A + ci) = make_float4(A[0], A[1], A[2], A[3]);
    *(float4*)(g_B + ci) = make_float4(hB[0], hB[1], hB[2], hB[3]);
}

// pass 2 folded into pass 3: each block rebuilds its chunk-prefix state from
// g_A/g_B (hot in L2), then re-runs its chunk emitting outputs.
__global__ void scan_p3(const float* __restrict__ h0, float* __restrict__ out)
{
    const int h  = (blockIdx.x * 128 + threadIdx.x) * 4;
    const int ch = blockIdx.y;
    const int b  = blockIdx.z;

    float4 x0 = *(const float4*)(h0 + b * HDIM + h);
    float hc[4] = {gfun(x0.x), gfun(x0.y), gfun(x0.z), gfun(x0.w)};
    for (int c = 0; c < ch; c++) {
        const size_t ci = ((size_t)(b * NCHUNK + c)) * HDIM + h;
        float4 Av = *(const float4*)(g_A + ci);
        float4 Bv = *(const float4*)(g_B + ci);
        hc[0] = fmaf(Av.x, hc[0], Bv.x);
        hc[1] = fmaf(Av.y, hc[1], Bv.y);
        hc[2] = fmaf(Av.z, hc[2], Bv.z);
        hc[3] = fmaf(Av.w, hc[3], Bv.w);
    }

    const size_t base = ((size_t)(b * S_LEN + ch * CHLEN)) * HDIM + h;
    const float* kp = g_k + base;
    const float* tp = g_t + base;
    float* op = out + base;
    for (int s0 = 0; s0 < CHLEN; s0 += 4) {
        float4 kk[4], tt[4];
#pragma unroll
        for (int j = 0; j < 4; j++) {
            kk[j] = *(const float4*)(kp + (size_t)(s0 + j) * HDIM);
            tt[j] = *(const float4*)(tp + (size_t)(s0 + j) * HDIM);
        }
#pragma unroll
        for (int j = 0; j < 4; j++) {
            float kv[4] = {kk[j].x, kk[j].y, kk[j].z, kk[j].w};
            float tv[4] = {tt[j].x, tt[j].y, tt[j].z, tt[j].w};
            float4 ov;
            float* o = (float*)&ov;
#pragma unroll
            for (int c = 0; c < 4; c++) {
                float z = sigf(kv[c]);
                hc[c] = fmaf(z, gfun(tv[c]) - hc[c], hc[c]);
                o[c] = hc[c];
            }
            *(float4*)(op + (size_t)(s0 + j) * HDIM) = ov;
        }
    }
}

// ---------------- launch ------------------------------------------------------
extern "C" void kernel_launch(void* const* d_in, const int* in_sizes, int n_in,
                              void* d_out, int out_size)
{
    const float* x  = (const float*)d_in[0];
    const float* h0 = (const float*)d_in[1];
    const float* Wz = (const float*)d_in[2];
    const float* bz = (const float*)d_in[3];
    const float* Wh = (const float*)d_in[4];
    const float* bh = (const float*)d_in[5];
    float* out = (float*)d_out;

    convert_all<<<(X_N4 + 2 * W_N4 + 255) / 256, 256>>>(x, Wz, Wh);

    dim3 ggrid(16, MROWS / 128);
    gemm_mma<<<ggrid, 256>>>(bz, bh);

    dim3 sgrid(HDIM / 512, NCHUNK, BATCH);   // 4 channels per thread
    scan_p1<<<sgrid, 128>>>();
    scan_p3<<<sgrid, 128>>>(h0, out);
}

// round 12
// speedup vs baseline: 1.4355x; 1.3674x over previous
#include <cuda_runtime.h>
#include <cuda_fp16.h>
#include <cstdint>
#include <cstddef>

#define S_LEN 4096
#define BATCH 8
#define DDIM  1024
#define HDIM  1024
#define MROWS (BATCH * S_LEN)   // 32768
#define NCHUNK 32
#define CHLEN  128              // S_LEN / NCHUNK

// ---------------- scratch (device globals; no allocations allowed) ----------
__device__ __half g_k16[(size_t)MROWS * HDIM];              // x@Wz^T+bz (fp16)
__device__ __half g_t16[(size_t)MROWS * HDIM];              // x@Wh^T+bh (fp16)
__device__ __half g_x16[(size_t)MROWS * DDIM];
__device__ __half g_wz16[(size_t)HDIM * DDIM];
__device__ __half g_wh16[(size_t)HDIM * DDIM];
__device__ float g_A[(size_t)BATCH * NCHUNK * HDIM];        // per-chunk prod(a)
__device__ float g_B[(size_t)BATCH * NCHUNK * HDIM];        // per-chunk h | h0=0

// ---------------- helpers ----------------------------------------------------
__device__ __forceinline__ uint32_t smem_u32(const void* p) {
    uint32_t a;
    asm("{ .reg .u64 t; cvta.to.shared.u64 t, %1; cvt.u32.u64 %0, t; }"
        : "=r"(a) : "l"(p));
    return a;
}
__device__ __forceinline__ void cp_async16(uint32_t dst, const void* src) {
    asm volatile("cp.async.cg.shared.global [%0], [%1], 16;"
                 :: "r"(dst), "l"(src) : "memory");
}
__device__ __forceinline__ void cp_commit() {
    asm volatile("cp.async.commit_group;" ::: "memory");
}
template <int N>
__device__ __forceinline__ void cp_wait() {
    asm volatile("cp.async.wait_group %0;" :: "n"(N) : "memory");
}
__device__ __forceinline__ void ldsm_x4(uint32_t& r0, uint32_t& r1,
                                        uint32_t& r2, uint32_t& r3, uint32_t addr) {
    asm volatile("ldmatrix.sync.aligned.m8n8.x4.shared.b16 {%0,%1,%2,%3}, [%4];"
                 : "=r"(r0), "=r"(r1), "=r"(r2), "=r"(r3) : "r"(addr));
}
__device__ __forceinline__ void mma16816(float* d, const uint32_t* a, const uint32_t* b) {
    asm volatile(
        "mma.sync.aligned.m16n8k16.row.col.f32.f16.f16.f32 "
        "{%0,%1,%2,%3}, {%4,%5,%6,%7}, {%8,%9}, {%0,%1,%2,%3};"
        : "+f"(d[0]), "+f"(d[1]), "+f"(d[2]), "+f"(d[3])
        : "r"(a[0]), "r"(a[1]), "r"(a[2]), "r"(a[3]), "r"(b[0]), "r"(b[1]));
}
__device__ __forceinline__ uint32_t sw128(uint32_t off) {
    return off ^ ((off >> 3) & 0x70);
}

__device__ __forceinline__ float sigf(float x) { return 1.f / (1.f + __expf(-x)); }
__device__ __forceinline__ float gfun(float x) { return (x >= 0.f) ? (x + 0.5f) : sigf(x); }

// ---------------- fp32 -> fp16 convert (one launch) --------------------------
#define X_N4  (MROWS * DDIM / 4)     // 8388608
#define W_N4  (HDIM * DDIM / 4)      // 262144
__global__ void convert_all(const float* __restrict__ x,
                            const float* __restrict__ Wz,
                            const float* __restrict__ Wh)
{
    int i = blockIdx.x * blockDim.x + threadIdx.x;
    const float* src;
    __half* dst;
    int idx;
    if (i < X_N4)                 { src = x;  dst = g_x16;  idx = i; }
    else if (i < X_N4 + W_N4)     { src = Wz; dst = g_wz16; idx = i - X_N4; }
    else if (i < X_N4 + 2 * W_N4) { src = Wh; dst = g_wh16; idx = i - X_N4 - W_N4; }
    else return;
    float4 v = ((const float4*)src)[idx];
    __half2* dp = (__half2*)(dst + (size_t)idx * 4);
    dp[0] = __halves2half2(__float2half_rn(v.x), __float2half_rn(v.y));
    dp[1] = __halves2half2(__float2half_rn(v.z), __float2half_rn(v.w));
}

// ---------------- HMMA GEMM (fp16 in, fp32 accum): C = X@W^T + bias ----------
// CTA 128x128, 8 warps 2(m) x 4(n), warp tile 64x32. K-chunk 64, SW128.
// 3-stage cp.async pipeline. K=1024 -> 16 chunks.
// Epilogue: bias add -> fp16 -> smem stage -> cooperative uint4 stores
// (16B/lane, fully coalesced; no MUFU, no narrow segments — fixes R8 failure).
#define KCH 64
#define NITER 16
#define STAGE_BYTES 32768
#define TSTRIDE 136   // halves per tile row (128 + 8 pad), 272B: uint4-aligned

__global__ void __launch_bounds__(256)
gemm_mma(const float* __restrict__ bz, const float* __restrict__ bh)
{
    __shared__ __align__(1024) uint8_t smem[3 * STAGE_BYTES];

    const int tid = threadIdx.x, wid = tid >> 5, lane = tid & 31;
    const int wm = wid >> 2, wn = wid & 3;     // 2 x 4 warp grid
    const bool is_z = (blockIdx.x < 8);
    const int n0 = (is_z ? blockIdx.x : blockIdx.x - 8) * 128;
    const int m0 = blockIdx.y * 128;
    const __half* W = is_z ? g_wz16 : g_wh16;
    const float* bias = is_z ? bz : bh;
    __half* C = is_z ? g_k16 : g_t16;

    const uint32_t sbase = smem_u32(smem);

    float acc[4][4][4];   // [mi][nj][frag]
#pragma unroll
    for (int i = 0; i < 4; i++)
#pragma unroll
        for (int j = 0; j < 4; j++)
#pragma unroll
            for (int f = 0; f < 4; f++) acc[i][j][f] = 0.f;

    auto issue = [&](int ch, int st) {
        const int kc = ch * KCH;
        const uint32_t stb = sbase + st * STAGE_BYTES;
#pragma unroll
        for (int i = 0; i < 4; i++) {
            int s = tid + i * 256;              // 1024 slots of 16B per tile
            int row = s >> 3, kslot = s & 7;
            uint32_t off = sw128(row * 128 + kslot * 16);
            cp_async16(stb + off,
                       g_x16 + (size_t)(m0 + row) * DDIM + kc + kslot * 8);
            cp_async16(stb + 16384 + off,
                       W + (size_t)(n0 + row) * DDIM + kc + kslot * 8);
        }
        cp_commit();
    };

    issue(0, 0);
    issue(1, 1);

    int st = 0;
    for (int ch = 0; ch < NITER; ch++) {
        if (ch + 2 < NITER) cp_wait<1>(); else cp_wait<0>();
        __syncthreads();
        if (ch + 2 < NITER) issue(ch + 2, (st + 2) % 3);

        const uint32_t aB = sbase + st * STAGE_BYTES;
        const uint32_t bB = aB + 16384;

#pragma unroll
        for (int ks = 0; ks < 4; ks++) {        // 4 x k16 per chunk
            uint32_t af[4][4], bf[2][4];
#pragma unroll
            for (int mi = 0; mi < 4; mi++) {
                int row = wm * 64 + mi * 16 + (lane & 15);
                uint32_t off = sw128(row * 128 + ks * 32 + (lane >> 4) * 16);
                ldsm_x4(af[mi][0], af[mi][1], af[mi][2], af[mi][3], aB + off);
            }
#pragma unroll
            for (int bj = 0; bj < 2; bj++) {
                int row = wn * 32 + bj * 16 + (lane & 7) + ((lane >> 4) & 1) * 8;
                uint32_t off = sw128(row * 128 + ks * 32 + ((lane >> 3) & 1) * 16);
                ldsm_x4(bf[bj][0], bf[bj][1], bf[bj][2], bf[bj][3], bB + off);
            }
#pragma unroll
            for (int mi = 0; mi < 4; mi++) {
#pragma unroll
                for (int bj = 0; bj < 2; bj++) {
                    mma16816(acc[mi][bj * 2],     af[mi], &bf[bj][0]);
                    mma16816(acc[mi][bj * 2 + 1], af[mi], &bf[bj][2]);
                }
            }
        }
        st = (st + 1) % 3;
    }

    // ---- epilogue: bias -> fp16 -> smem stage -> coalesced uint4 stores ----
    __syncthreads();
    __half* tile = (__half*)smem;   // 128 x TSTRIDE halves = 34 KB (< 96 KB)
#pragma unroll
    for (int mi = 0; mi < 4; mi++) {
#pragma unroll
        for (int nj = 0; nj < 4; nj++) {
            int r = wm * 64 + mi * 16 + (lane >> 2);
            int c = wn * 32 + nj * 8 + (lane & 3) * 2;
            float2 bv = *(const float2*)(bias + n0 + c);
            __half2 v0 = __floats2half2_rn(acc[mi][nj][0] + bv.x,
                                           acc[mi][nj][1] + bv.y);
            __half2 v1 = __floats2half2_rn(acc[mi][nj][2] + bv.x,
                                           acc[mi][nj][3] + bv.y);
            *(__half2*)(tile + r * TSTRIDE + c) = v0;
            *(__half2*)(tile + (r + 8) * TSTRIDE + c) = v1;
        }
    }
    __syncthreads();
#pragma unroll
    for (int it = 0; it < 8; it++) {
        int id = tid + it * 256;            // 2048 chunks of 8 halves
        int row = id >> 4, c8 = (id & 15) * 8;
        uint4 v = *(const uint4*)(tile + row * TSTRIDE + c8);
        *(uint4*)(C + (size_t)(m0 + row) * HDIM + n0 + c8) = v;
    }
}

// ---------------- scan: h_t = (1-z_t) h_{t-1} + z_t g(t_t) -------------------
// 2 channels per thread via half2 loads; 1024 CTAs (occupancy vs vector-width
// balance: R7 scalar/2048 = 158us total, R9 float4/512 regressed).
__global__ void scan_p1()
{
    const int h  = (blockIdx.x * 128 + threadIdx.x) * 2;
    const int ch = blockIdx.y;
    const int b  = blockIdx.z;
    const size_t base = ((size_t)(b * S_LEN + ch * CHLEN)) * HDIM + h;
    const __half* kp = g_k16 + base;
    const __half* tp = g_t16 + base;
    float A0 = 1.f, A1 = 1.f, B0 = 0.f, B1 = 0.f;
    for (int s0 = 0; s0 < CHLEN; s0 += 8) {
        __half2 kk[8], tt[8];
#pragma unroll
        for (int j = 0; j < 8; j++) {
            kk[j] = *(const __half2*)(kp + (size_t)(s0 + j) * HDIM);
            tt[j] = *(const __half2*)(tp + (size_t)(s0 + j) * HDIM);
        }
#pragma unroll
        for (int j = 0; j < 8; j++) {
            float2 kv = __half22float2(kk[j]);
            float2 tv = __half22float2(tt[j]);
            float z0 = sigf(kv.x), z1 = sigf(kv.y);
            float a0 = 1.f - z0,   a1 = 1.f - z1;
            B0 = fmaf(a0, B0, z0 * gfun(tv.x));
            B1 = fmaf(a1, B1, z1 * gfun(tv.y));
            A0 *= a0; A1 *= a1;
        }
    }
    const size_t ci = ((size_t)(b * NCHUNK + ch)) * HDIM + h;
    *(float2*)(g_A + ci) = make_float2(A0, A1);
    *(float2*)(g_B + ci) = make_float2(B0, B1);
}

// pass 2 folded into pass 3: each block rebuilds its chunk-prefix state from
// g_A/g_B (hot in L2), then re-runs its chunk emitting outputs.
__global__ void scan_p3(const float* __restrict__ h0, float* __restrict__ out)
{
    const int h  = (blockIdx.x * 128 + threadIdx.x) * 2;
    const int ch = blockIdx.y;
    const int b  = blockIdx.z;

    float2 x0 = *(const float2*)(h0 + b * HDIM + h);
    float h0c = gfun(x0.x), h1c = gfun(x0.y);
    for (int c = 0; c < ch; c++) {
        const size_t ci = ((size_t)(b * NCHUNK + c)) * HDIM + h;
        float2 Av = *(const float2*)(g_A + ci);
        float2 Bv = *(const float2*)(g_B + ci);
        h0c = fmaf(Av.x, h0c, Bv.x);
        h1c = fmaf(Av.y, h1c, Bv.y);
    }

    const size_t base = ((size_t)(b * S_LEN + ch * CHLEN)) * HDIM + h;
    const __half* kp = g_k16 + base;
    const __half* tp = g_t16 + base;
    float* op = out + base;
    for (int s0 = 0; s0 < CHLEN; s0 += 8) {
        __half2 kk[8], tt[8];
#pragma unroll
        for (int j = 0; j < 8; j++) {
            kk[j] = *(const __half2*)(kp + (size_t)(s0 + j) * HDIM);
            tt[j] = *(const __half2*)(tp + (size_t)(s0 + j) * HDIM);
        }
#pragma unroll
        for (int j = 0; j < 8; j++) {
            float2 kv = __half22float2(kk[j]);
            float2 tv = __half22float2(tt[j]);
            float z0 = sigf(kv.x), z1 = sigf(kv.y);
            h0c = fmaf(z0, gfun(tv.x) - h0c, h0c);
            h1c = fmaf(z1, gfun(tv.y) - h1c, h1c);
            *(float2*)(op + (size_t)(s0 + j) * HDIM) = make_float2(h0c, h1c);
        }
    }
}

// ---------------- launch ------------------------------------------------------
extern "C" void kernel_launch(void* const* d_in, const int* in_sizes, int n_in,
                              void* d_out, int out_size)
{
    const float* x  = (const float*)d_in[0];
    const float* h0 = (const float*)d_in[1];
    const float* Wz = (const float*)d_in[2];
    const float* bz = (const float*)d_in[3];
    const float* Wh = (const float*)d_in[4];
    const float* bh = (const float*)d_in[5];
    float* out = (float*)d_out;

    convert_all<<<(X_N4 + 2 * W_N4 + 255) / 256, 256>>>(x, Wz, Wh);

    dim3 ggrid(16, MROWS / 128);
    gemm_mma<<<ggrid, 256>>>(bz, bh);

    dim3 sgrid(HDIM / 256, NCHUNK, BATCH);   // 2 channels per thread, 1024 CTAs
    scan_p1<<<sgrid, 128>>>();
    scan_p3<<<sgrid, 128>>>(h0, out);
}